// round 15
// baseline (speedup 1.0000x reference)
#include <cuda_runtime.h>
#include <cuda_fp16.h>
#include <cstdint>

constexpr int NN = 100000;    // nodes
constexpr int NE = 3200000;   // edges
constexpr int CIN = 512;
constexpr int CH  = 40;
constexpr int COUT = 20;

constexpr int SCAN_B  = 1024;
constexpr int SCAN_NB = (NN + SCAN_B - 1) / SCAN_B;   // 98

// Scratch (__device__ globals: allocation-free per harness rules)
__device__ __align__(16) __half g_h1[(size_t)NN * CH];    // fp16 messages L1
__device__ __align__(16) float  g_acc1[(size_t)NN * CH];  // fp32 accumulator
__device__ __align__(16) __half g_h2[(size_t)NN * COUT];  // fp16 messages L2
__device__ __align__(16) float  g_wpair[CIN * CH];        // k-interleaved W1
__device__ float g_dinv[NN];
__device__ int   g_deg[NN];       // in-degree WITHOUT self loop
__device__ int   g_rowstart[NN];
__device__ int   g_cursor[NN];
__device__ int   g_csr[NE];       // src ids grouped by dst
__device__ int   g_scan[NN];
__device__ int   g_bsum[SCAN_NB];

// ---------------------------------------------------------------------------
// helpers
// ---------------------------------------------------------------------------
__device__ __forceinline__ unsigned long long ffma2(unsigned long long a,
                                                    unsigned long long b,
                                                    unsigned long long c) {
    unsigned long long d;
    asm("fma.rn.f32x2 %0, %1, %2, %3;" : "=l"(d) : "l"(a), "l"(b), "l"(c));
    return d;
}

__device__ __forceinline__ void cp_async16(uint32_t dst_smem, const void* src,
                                           int src_bytes) {
    asm volatile("cp.async.cg.shared.global [%0], [%1], 16, %2;"
                 :: "r"(dst_smem), "l"(src), "r"(src_bytes));
}
__device__ __forceinline__ void cp_commit() {
    asm volatile("cp.async.commit_group;");
}
template <int N>
__device__ __forceinline__ void cp_wait() {
    asm volatile("cp.async.wait_group %0;" :: "n"(N));
}

__device__ __forceinline__ uint32_t smem_u32(const void* p) {
    uint32_t a;
    asm("{ .reg .u64 t; cvta.to.shared.u64 t, %1; cvt.u32.u64 %0, t; }"
        : "=r"(a) : "l"(p));
    return a;
}

// add 4 fp16 pairs (uint4) into 8 fp32 accumulators
__device__ __forceinline__ void acc8_h(const uint4 v, float* a) {
    float2 f0 = __half22float2(*(const __half2*)&v.x);
    float2 f1 = __half22float2(*(const __half2*)&v.y);
    float2 f2 = __half22float2(*(const __half2*)&v.z);
    float2 f3 = __half22float2(*(const __half2*)&v.w);
    a[0] += f0.x; a[1] += f0.y; a[2] += f1.x; a[3] += f1.y;
    a[4] += f2.x; a[5] += f2.y; a[6] += f3.x; a[7] += f3.y;
}

__device__ __forceinline__ void acc4_h(const uint2 v, float* a) {
    float2 f0 = __half22float2(*(const __half2*)&v.x);
    float2 f1 = __half22float2(*(const __half2*)&v.y);
    a[0] += f0.x; a[1] += f0.y; a[2] += f1.x; a[3] += f1.y;
}

// ---------------------------------------------------------------------------
// degree / dinv / CSR build
// ---------------------------------------------------------------------------
__global__ void k_deg_init() {
    int i = blockIdx.x * 256 + threadIdx.x;
    if (i < NN) g_deg[i] = 0;
}
__global__ void k_deg_count(const int* __restrict__ ei) {
    int e = blockIdx.x * 256 + threadIdx.x;
    if (e < NE) atomicAdd(&g_deg[ei[NE + e]], 1);
}
__global__ void k_dinv() {
    int i = blockIdx.x * 256 + threadIdx.x;
    if (i < NN) g_dinv[i] = rsqrtf((float)(g_deg[i] + 1));  // +1 self loop
}

// W1 -> k-pair interleaved layout: wp[k2*2*CH + c*2 + p] = W1[(2*k2+p)*CH + c]
__global__ void k_wpair(const float* __restrict__ W1) {
    int idx = blockIdx.x * 256 + threadIdx.x;
    if (idx < (CIN / 2) * CH) {
        int k2 = idx / CH, c = idx - k2 * CH;
        g_wpair[k2 * 2 * CH + c * 2]     = W1[(2 * k2) * CH + c];
        g_wpair[k2 * 2 * CH + c * 2 + 1] = W1[(2 * k2 + 1) * CH + c];
    }
}

// --- parallel scan, phase 1: per-block inclusive scan + block totals -------
__global__ __launch_bounds__(SCAN_B) void k_scan1() {
    const int t = threadIdx.x, b = blockIdx.x;
    const int i = b * SCAN_B + t;
    int v = (i < NN) ? g_deg[i] : 0;
    const int lane = t & 31, warp = t >> 5;
    int s = v;
#pragma unroll
    for (int o = 1; o < 32; o <<= 1) {
        int u = __shfl_up_sync(~0u, s, o);
        if (lane >= o) s += u;
    }
    __shared__ int wsum[32];
    if (lane == 31) wsum[warp] = s;
    __syncthreads();
    if (warp == 0) {
        int ws = wsum[lane];
#pragma unroll
        for (int o = 1; o < 32; o <<= 1) {
            int u = __shfl_up_sync(~0u, ws, o);
            if (lane >= o) ws += u;
        }
        wsum[lane] = ws;
    }
    __syncthreads();
    int incl = s + (warp ? wsum[warp - 1] : 0);
    if (i < NN) g_scan[i] = incl;
    if (t == SCAN_B - 1) g_bsum[b] = incl;
}

// --- phase 2: exclusive scan of the 98 block totals ------------------------
__global__ __launch_bounds__(128) void k_scan2() {
    const int t = threadIdx.x;
    int v = (t < SCAN_NB) ? g_bsum[t] : 0;
    const int lane = t & 31, warp = t >> 5;
    int s = v;
#pragma unroll
    for (int o = 1; o < 32; o <<= 1) {
        int u = __shfl_up_sync(~0u, s, o);
        if (lane >= o) s += u;
    }
    __shared__ int wsum[4];
    if (lane == 31) wsum[warp] = s;
    __syncthreads();
    int add = 0;
    for (int w = 0; w < warp; w++) add += wsum[w];
    int incl = s + add;
    if (t < SCAN_NB) g_bsum[t] = incl - v;   // exclusive block offset
}

// --- phase 3: rowstart / cursor --------------------------------------------
__global__ __launch_bounds__(SCAN_B) void k_scan3() {
    const int t = threadIdx.x, b = blockIdx.x;
    const int i = b * SCAN_B + t;
    if (i < NN) {
        int rs = g_bsum[b] + g_scan[i] - g_deg[i];
        g_rowstart[i] = rs;
        g_cursor[i] = rs;
    }
}

__global__ void k_fill(const int* __restrict__ ei) {
    int e = blockIdx.x * 256 + threadIdx.x;
    if (e < NE) {
        int s = ei[e];
        int d = ei[NE + e];
        int p = atomicAdd(&g_cursor[d], 1);
        g_csr[p] = s;
    }
}

// ---------------------------------------------------------------------------
// GEMM1 (k-parity f32x2): hs1 = dinv * (x @ W1) -> fp16.
// 64 threads/block, 64 rows/block. Thread: 4 rows (stride 16: r*16+rp) x
// 10 cols. Accumulator pair = (even-k, odd-k) partial sums; summed at end.
// x pairs are natural LDS.64 (k-contiguous); W pairs from g_wpair.
// ---------------------------------------------------------------------------
constexpr int KT = 16;               // k per tile (8 pairs)
constexpr int NT = CIN / KT;         // 32 tiles
constexpr int RT = 64;               // rows per block
constexpr int XROW = 20;             // padded floats per row (16 used)

__global__ __launch_bounds__(64) void k_gemm1(const float* __restrict__ x) {
    __shared__ __align__(16) float xs[2][RT * XROW];   // 2 x 5 KB
    __shared__ __align__(16) float ws[2][(KT / 2) * 2 * CH];  // 2 x 2.5 KB

    const int tid = threadIdx.x;
    const int rp = tid >> 2;          // 0..15 : rows rp, rp+16, rp+32, rp+48
    const int ct = tid & 3;           // 0..3  : cols ct*10 .. ct*10+9
    const int row0 = blockIdx.x * RT;

    const uint32_t xs_b[2] = { smem_u32(&xs[0][0]), smem_u32(&xs[1][0]) };
    const uint32_t ws_b[2] = { smem_u32(&ws[0][0]), smem_u32(&ws[1][0]) };

    auto stage = [&](int t) {
        int kt = t * KT;
        int buf = t & 1;
        // x tile: 64 rows x 4 chunks(16B) = 256 chunks, 4 per thread
#pragma unroll
        for (int i = 0; i < 4; i++) {
            int idx = tid + 64 * i;         // 0..255
            int r = idx >> 2;
            int q = idx & 3;
            int gr = row0 + r;
            const float* src = x + (size_t)gr * CIN + kt + q * 4;
            uint32_t dst = xs_b[buf] + (uint32_t)(r * XROW + q * 4) * 4u;
            cp_async16(dst, src, (gr < NN) ? 16 : 0);
        }
        // w tile: 8 k-pairs x 80 floats = 640 floats = 160 chunks (contiguous)
#pragma unroll
        for (int i = 0; i < 3; i++) {
            int idx = tid + 64 * i;
            if (idx < 160)
                cp_async16(ws_b[buf] + (uint32_t)idx * 16u,
                           g_wpair + t * (KT * CH) + idx * 4, 16);
        }
    };

    unsigned long long acc[4][10];
#pragma unroll
    for (int r = 0; r < 4; r++)
#pragma unroll
        for (int j = 0; j < 10; j++) acc[r][j] = 0ull;

    stage(0);
    cp_commit();

    for (int t = 0; t < NT; t++) {
        int buf = t & 1;
        if (t + 1 < NT) {
            stage(t + 1);
            cp_commit();
            cp_wait<1>();
        } else {
            cp_wait<0>();
        }
        __syncthreads();

        const float* xsb = &xs[buf][0];
        const float* wsb = &ws[buf][0];
#pragma unroll
        for (int k2 = 0; k2 < KT / 2; k2++) {
            unsigned long long wv[10];
            const float* wk = wsb + k2 * 2 * CH + ct * 20;
#pragma unroll
            for (int j = 0; j < 10; j++)
                wv[j] = *(const unsigned long long*)(wk + 2 * j);
            unsigned long long xv[4];
#pragma unroll
            for (int r = 0; r < 4; r++)
                xv[r] = *(const unsigned long long*)(xsb + (r * 16 + rp) * XROW + k2 * 2);
#pragma unroll
            for (int r = 0; r < 4; r++)
#pragma unroll
                for (int j = 0; j < 10; j++)
                    acc[r][j] = ffma2(xv[r], wv[j], acc[r][j]);
        }
        __syncthreads();
    }

    // epilogue: sum k-parity halves, scale by dinv, quantize to fp16
#pragma unroll
    for (int r = 0; r < 4; r++) {
        int gr = row0 + r * 16 + rp;
        if (gr < NN) {
            float dv = g_dinv[gr];
            float o[10];
#pragma unroll
            for (int j = 0; j < 10; j++) {
                unsigned long long a = acc[r][j];
                o[j] = (__uint_as_float((unsigned)a) +
                        __uint_as_float((unsigned)(a >> 32))) * dv;
            }
#pragma unroll
            for (int m = 0; m < 5; m++) {
                int c = ct * 10 + 2 * m;
                *(__half2*)&g_h1[(size_t)gr * CH + c] =
                    __floats2half2_rn(o[2 * m], o[2 * m + 1]);
            }
        }
    }
}

// ---------------------------------------------------------------------------
// Aggregation layer 1 (PULL, fp16 msgs): 5 threads/node, each owns 8 channels
// (one uint4 = 4 half2). Accumulate fp32, single fp32 write to g_acc1.
// ---------------------------------------------------------------------------
__global__ void k_agg1() {
    unsigned t = blockIdx.x * 256u + threadIdx.x;
    unsigned node = t / 5u;
    if (node >= (unsigned)NN) return;
    unsigned q = t - node * 5u;
    const uint4* base = (const uint4*)g_h1;   // node stride = 5 uint4

    float a[8];
#pragma unroll
    for (int i = 0; i < 8; i++) a[i] = 0.f;
    acc8_h(base[(size_t)node * 5 + q], a);    // self term

    int beg = g_rowstart[node];
    int len = g_deg[node];
    int i = 0;
    for (; i + 2 <= len; i += 2) {
        int s0 = __ldg(&g_csr[beg + i]);
        int s1 = __ldg(&g_csr[beg + i + 1]);
        uint4 v0 = base[(size_t)s0 * 5 + q];
        uint4 v1 = base[(size_t)s1 * 5 + q];
        acc8_h(v0, a);
        acc8_h(v1, a);
    }
    if (i < len) {
        int s0 = __ldg(&g_csr[beg + i]);
        acc8_h(base[(size_t)s0 * 5 + q], a);
    }

    float4* dst = (float4*)&g_acc1[(size_t)node * CH + q * 8];
    dst[0] = make_float4(a[0], a[1], a[2], a[3]);
    dst[1] = make_float4(a[4], a[5], a[6], a[7]);
}

// ---------------------------------------------------------------------------
// Layer-1 finish + GEMM2: r = relu(dinv*acc1 + b1); hs2 = dinv*(r @ W2) -> fp16
// ---------------------------------------------------------------------------
__global__ __launch_bounds__(128) void k_layer2(const float* __restrict__ W2,
                                                const float* __restrict__ b1) {
    __shared__ float w2s[CH * COUT];
    __shared__ float b1s[CH];
    int tid = threadIdx.x;
    for (int i = tid; i < CH * COUT; i += 128) w2s[i] = W2[i];
    if (tid < CH) b1s[tid] = b1[tid];
    __syncthreads();

    int r = blockIdx.x * 128 + tid;
    if (r >= NN) return;
    float dv = g_dinv[r];

    float rv[CH];
#pragma unroll
    for (int q = 0; q < 10; q++) {
        float4 v = *(const float4*)&g_acc1[(size_t)r * CH + q * 4];
        rv[4 * q + 0] = fmaxf(dv * v.x + b1s[4 * q + 0], 0.f);
        rv[4 * q + 1] = fmaxf(dv * v.y + b1s[4 * q + 1], 0.f);
        rv[4 * q + 2] = fmaxf(dv * v.z + b1s[4 * q + 2], 0.f);
        rv[4 * q + 3] = fmaxf(dv * v.w + b1s[4 * q + 3], 0.f);
    }

    float acc[COUT];
#pragma unroll
    for (int c = 0; c < COUT; c++) acc[c] = 0.f;
#pragma unroll
    for (int k = 0; k < CH; k++) {
        float xv = rv[k];
#pragma unroll
        for (int c = 0; c < COUT; c++)
            acc[c] = fmaf(xv, w2s[k * COUT + c], acc[c]);
    }

#pragma unroll
    for (int p = 0; p < 10; p++) {
        __half2 h = __floats2half2_rn(dv * acc[2 * p], dv * acc[2 * p + 1]);
        *(__half2*)&g_h2[(size_t)r * COUT + 2 * p] = h;
    }
}

// ---------------------------------------------------------------------------
// Aggregation layer 2 (PULL, fp16 msgs) fused with final epilogue:
// 5 threads/node, each owns 4 channels (uint2 = 2 half2).
// out = dinv * (self + sum neighbors) + b2
// ---------------------------------------------------------------------------
__global__ void k_agg2(float* __restrict__ out, const float* __restrict__ b2) {
    unsigned t = blockIdx.x * 256u + threadIdx.x;
    unsigned node = t / 5u;
    if (node >= (unsigned)NN) return;
    unsigned q = t - node * 5u;
    const uint2* base = (const uint2*)g_h2;   // node stride = 5 uint2

    float a[4];
#pragma unroll
    for (int i = 0; i < 4; i++) a[i] = 0.f;
    acc4_h(base[(size_t)node * 5 + q], a);    // self term

    int beg = g_rowstart[node];
    int len = g_deg[node];
    int i = 0;
    for (; i + 2 <= len; i += 2) {
        int s0 = __ldg(&g_csr[beg + i]);
        int s1 = __ldg(&g_csr[beg + i + 1]);
        uint2 v0 = base[(size_t)s0 * 5 + q];
        uint2 v1 = base[(size_t)s1 * 5 + q];
        acc4_h(v0, a);
        acc4_h(v1, a);
    }
    if (i < len) {
        int s0 = __ldg(&g_csr[beg + i]);
        acc4_h(base[(size_t)s0 * 5 + q], a);
    }

    float dv = g_dinv[node];
    float4 b = *(const float4*)&b2[q * 4];
    float4 o = make_float4(dv * a[0] + b.x, dv * a[1] + b.y,
                           dv * a[2] + b.z, dv * a[3] + b.w);
    ((float4*)out)[(size_t)node * 5 + q] = o;
}

// ---------------------------------------------------------------------------
extern "C" void kernel_launch(void* const* d_in, const int* in_sizes, int n_in,
                              void* d_out, int out_size) {
    const float* x  = (const float*)d_in[0];
    const int*   ei = (const int*)d_in[1];
    const float* W1 = (const float*)d_in[2];
    const float* b1 = (const float*)d_in[3];
    const float* W2 = (const float*)d_in[4];
    const float* b2 = (const float*)d_in[5];
    float* out = (float*)d_out;

    k_deg_init<<<(NN + 255) / 256, 256>>>();
    k_deg_count<<<(NE + 255) / 256, 256>>>(ei);
    k_dinv<<<(NN + 255) / 256, 256>>>();
    k_wpair<<<((CIN / 2) * CH + 255) / 256, 256>>>(W1);
    k_scan1<<<SCAN_NB, SCAN_B>>>();
    k_scan2<<<1, 128>>>();
    k_scan3<<<SCAN_NB, SCAN_B>>>();
    k_fill<<<(NE + 255) / 256, 256>>>(ei);
    k_gemm1<<<(NN + RT - 1) / RT, 64>>>(x);
    {
        long long th = (long long)NN * 5;
        k_agg1<<<(unsigned)((th + 255) / 256), 256>>>();
    }
    k_layer2<<<(NN + 127) / 128, 128>>>(W2, b1);
    {
        long long th = (long long)NN * 5;
        k_agg2<<<(unsigned)((th + 255) / 256), 256>>>(out, b2);
    }
}

// round 16
// speedup vs baseline: 1.3132x; 1.3132x over previous
#include <cuda_runtime.h>
#include <cuda_fp16.h>
#include <cstdint>

constexpr int NN = 100000;    // nodes
constexpr int NE = 3200000;   // edges
constexpr int CIN = 512;
constexpr int CH  = 40;
constexpr int COUT = 20;

constexpr int SCAN_B  = 1024;
constexpr int SCAN_NB = (NN + SCAN_B - 1) / SCAN_B;   // 98

// Scratch (__device__ globals: allocation-free per harness rules)
__device__ __align__(16) __half g_h1[(size_t)NN * CH];    // fp16 messages L1
__device__ __align__(16) float  g_acc1[(size_t)NN * CH];  // fp32 accumulator
__device__ __align__(16) __half g_h2[(size_t)NN * COUT];  // fp16 messages L2
__device__ __align__(16) uint32_t g_wfrag[32 * 5 * 32 * 2]; // W1 in B-fragment order
__device__ float g_dinv[NN];
__device__ int   g_deg[NN];       // in-degree WITHOUT self loop
__device__ int   g_rowstart[NN];
__device__ int   g_cursor[NN];
__device__ int   g_csr[NE];       // src ids grouped by dst
__device__ int   g_scan[NN];
__device__ int   g_bsum[SCAN_NB];

// ---------------------------------------------------------------------------
// helpers
// ---------------------------------------------------------------------------
__device__ __forceinline__ void cp_async16(uint32_t dst_smem, const void* src,
                                           int src_bytes) {
    asm volatile("cp.async.cg.shared.global [%0], [%1], 16, %2;"
                 :: "r"(dst_smem), "l"(src), "r"(src_bytes));
}
__device__ __forceinline__ void cp_commit() {
    asm volatile("cp.async.commit_group;");
}
template <int N>
__device__ __forceinline__ void cp_wait() {
    asm volatile("cp.async.wait_group %0;" :: "n"(N));
}

__device__ __forceinline__ uint32_t smem_u32(const void* p) {
    uint32_t a;
    asm("{ .reg .u64 t; cvta.to.shared.u64 t, %1; cvt.u32.u64 %0, t; }"
        : "=r"(a) : "l"(p));
    return a;
}

__device__ __forceinline__ uint32_t pack_h2(float lo, float hi) {
    __half2 h = __floats2half2_rn(lo, hi);
    return *(uint32_t*)&h;
}

// add 4 fp16 pairs (uint4) into 8 fp32 accumulators
__device__ __forceinline__ void acc8_h(const uint4 v, float* a) {
    float2 f0 = __half22float2(*(const __half2*)&v.x);
    float2 f1 = __half22float2(*(const __half2*)&v.y);
    float2 f2 = __half22float2(*(const __half2*)&v.z);
    float2 f3 = __half22float2(*(const __half2*)&v.w);
    a[0] += f0.x; a[1] += f0.y; a[2] += f1.x; a[3] += f1.y;
    a[4] += f2.x; a[5] += f2.y; a[6] += f3.x; a[7] += f3.y;
}

__device__ __forceinline__ void acc4_h(const uint2 v, float* a) {
    float2 f0 = __half22float2(*(const __half2*)&v.x);
    float2 f1 = __half22float2(*(const __half2*)&v.y);
    a[0] += f0.x; a[1] += f0.y; a[2] += f1.x; a[3] += f1.y;
}

// ---------------------------------------------------------------------------
// degree / dinv / CSR build
// ---------------------------------------------------------------------------
__global__ void k_deg_init() {
    int i = blockIdx.x * 256 + threadIdx.x;
    if (i < NN) g_deg[i] = 0;
}
__global__ void k_deg_count(const int* __restrict__ ei) {
    int e = blockIdx.x * 256 + threadIdx.x;
    if (e < NE) atomicAdd(&g_deg[ei[NE + e]], 1);
}
__global__ void k_dinv() {
    int i = blockIdx.x * 256 + threadIdx.x;
    if (i < NN) g_dinv[i] = rsqrtf((float)(g_deg[i] + 1));  // +1 self loop
}

// W1 -> fp16 B-fragment order for mma.m16n8k16:
// g_wfrag[((s*5+nt)*32+l)*2+w] = half2( W1[k][n], W1[k+1][n] )
//   with k = s*16 + (l%4)*2 + w*8, n = nt*8 + l/4
__global__ void k_wfrag(const float* __restrict__ W1) {
    int idx = blockIdx.x * 256 + threadIdx.x;   // 0..5119
    if (idx >= 32 * 5 * 32) return;
    int l = idx & 31;
    int nt = (idx >> 5) % 5;
    int s = idx / 160;
    int n = nt * 8 + (l >> 2);
    int kb = s * 16 + (l & 3) * 2;
#pragma unroll
    for (int w = 0; w < 2; w++) {
        int k = kb + w * 8;
        g_wfrag[idx * 2 + w] = pack_h2(W1[k * CH + n], W1[(k + 1) * CH + n]);
    }
}

// --- parallel scan, phase 1: per-block inclusive scan + block totals -------
__global__ __launch_bounds__(SCAN_B) void k_scan1() {
    const int t = threadIdx.x, b = blockIdx.x;
    const int i = b * SCAN_B + t;
    int v = (i < NN) ? g_deg[i] : 0;
    const int lane = t & 31, warp = t >> 5;
    int s = v;
#pragma unroll
    for (int o = 1; o < 32; o <<= 1) {
        int u = __shfl_up_sync(~0u, s, o);
        if (lane >= o) s += u;
    }
    __shared__ int wsum[32];
    if (lane == 31) wsum[warp] = s;
    __syncthreads();
    if (warp == 0) {
        int ws = wsum[lane];
#pragma unroll
        for (int o = 1; o < 32; o <<= 1) {
            int u = __shfl_up_sync(~0u, ws, o);
            if (lane >= o) ws += u;
        }
        wsum[lane] = ws;
    }
    __syncthreads();
    int incl = s + (warp ? wsum[warp - 1] : 0);
    if (i < NN) g_scan[i] = incl;
    if (t == SCAN_B - 1) g_bsum[b] = incl;
}

// --- phase 2: exclusive scan of the 98 block totals ------------------------
__global__ __launch_bounds__(128) void k_scan2() {
    const int t = threadIdx.x;
    int v = (t < SCAN_NB) ? g_bsum[t] : 0;
    const int lane = t & 31, warp = t >> 5;
    int s = v;
#pragma unroll
    for (int o = 1; o < 32; o <<= 1) {
        int u = __shfl_up_sync(~0u, s, o);
        if (lane >= o) s += u;
    }
    __shared__ int wsum[4];
    if (lane == 31) wsum[warp] = s;
    __syncthreads();
    int add = 0;
    for (int w = 0; w < warp; w++) add += wsum[w];
    int incl = s + add;
    if (t < SCAN_NB) g_bsum[t] = incl - v;   // exclusive block offset
}

// --- phase 3: rowstart / cursor --------------------------------------------
__global__ __launch_bounds__(SCAN_B) void k_scan3() {
    const int t = threadIdx.x, b = blockIdx.x;
    const int i = b * SCAN_B + t;
    if (i < NN) {
        int rs = g_bsum[b] + g_scan[i] - g_deg[i];
        g_rowstart[i] = rs;
        g_cursor[i] = rs;
    }
}

__global__ void k_fill(const int* __restrict__ ei) {
    int e = blockIdx.x * 256 + threadIdx.x;
    if (e < NE) {
        int s = ei[e];
        int d = ei[NE + e];
        int p = atomicAdd(&g_cursor[d], 1);
        g_csr[p] = s;
    }
}

// ---------------------------------------------------------------------------
// GEMM1 via mma.sync.m16n8k16 (fp16 in, fp32 acc): hs1 = dinv*(x@W1) -> fp16
// 256 threads / 8 warps / 128 rows per block. Warp w owns rows w*16..w*16+15,
// all 40 cols (5 n-tiles). K loop = 16 tiles of KT=32 (2 k16 steps each).
// x fp32 staged by cp.async (XROW=40 pad); A fragments converted in regs.
// W pre-packed in exact B-fragment order (g_wfrag) -> one LDS.64 per tile.
// ---------------------------------------------------------------------------
constexpr int KT = 32;               // k per tile (2 mma k-steps)
constexpr int NTL = CIN / KT;        // 16 tiles
constexpr int RT = 128;              // rows per block
constexpr int XROW = 40;             // padded floats per row

__global__ __launch_bounds__(256) void k_gemm1(const float* __restrict__ x) {
    __shared__ __align__(16) float    xs[2][RT * XROW];   // 2 x 20 KB
    __shared__ __align__(16) uint32_t ws[2][2 * 5 * 32 * 2]; // 2 x 2.5 KB

    const int tid = threadIdx.x;
    const int l = tid & 31;           // lane
    const int wp = tid >> 5;          // warp 0..7
    const int gid = l >> 2;           // 0..7
    const int ctid = l & 3;           // 0..3
    const int row0 = blockIdx.x * RT;

    const uint32_t xs_b[2] = { smem_u32(&xs[0][0]), smem_u32(&xs[1][0]) };
    const uint32_t ws_b[2] = { smem_u32(&ws[0][0]), smem_u32(&ws[1][0]) };

    auto stage = [&](int t) {
        int buf = t & 1;
        // x tile: 128 rows x 8 chunks(16B) = 1024 chunks, 4 per thread
#pragma unroll
        for (int i = 0; i < 4; i++) {
            int idx = tid + 256 * i;
            int r = idx >> 3;
            int q = idx & 7;
            int gr = row0 + r;
            const float* src = x + (size_t)gr * CIN + t * KT + q * 4;
            uint32_t dst = xs_b[buf] + (uint32_t)(r * XROW + q * 4) * 4u;
            cp_async16(dst, src, (gr < NN) ? 16 : 0);
        }
        // w fragments for this tile: 640 u32 = 160 chunks of 16B
        if (tid < 160)
            cp_async16(ws_b[buf] + (uint32_t)tid * 16u,
                       g_wfrag + t * 640 + tid * 4, 16);
    };

    float c[5][4];
#pragma unroll
    for (int nt = 0; nt < 5; nt++)
#pragma unroll
        for (int j = 0; j < 4; j++) c[nt][j] = 0.f;

    stage(0);
    cp_commit();

    for (int t = 0; t < NTL; t++) {
        int buf = t & 1;
        if (t + 1 < NTL) {
            stage(t + 1);
            cp_commit();
            cp_wait<1>();
        } else {
            cp_wait<0>();
        }
        __syncthreads();

        const float* xsb = &xs[buf][0];
        const uint32_t* wsb = &ws[buf][0];
#pragma unroll
        for (int ks = 0; ks < 2; ks++) {
            // A fragments: rows (wp*16+gid, +8), cols ks*16 + ctid*2 (+8)
            const float* xr = xsb + (wp * 16 + gid) * XROW + ks * 16 + ctid * 2;
            float2 f00 = *(const float2*)(xr);
            float2 f10 = *(const float2*)(xr + 8 * XROW);
            float2 f01 = *(const float2*)(xr + 8);
            float2 f11 = *(const float2*)(xr + 8 * XROW + 8);
            uint32_t a0 = pack_h2(f00.x, f00.y);
            uint32_t a1 = pack_h2(f10.x, f10.y);
            uint32_t a2 = pack_h2(f01.x, f01.y);
            uint32_t a3 = pack_h2(f11.x, f11.y);
#pragma unroll
            for (int nt = 0; nt < 5; nt++) {
                uint2 bb = *(const uint2*)(wsb + ((ks * 5 + nt) * 32 + l) * 2);
                asm volatile(
                    "mma.sync.aligned.m16n8k16.row.col.f32.f16.f16.f32 "
                    "{%0,%1,%2,%3}, {%4,%5,%6,%7}, {%8,%9}, {%0,%1,%2,%3};"
                    : "+f"(c[nt][0]), "+f"(c[nt][1]),
                      "+f"(c[nt][2]), "+f"(c[nt][3])
                    : "r"(a0), "r"(a1), "r"(a2), "r"(a3),
                      "r"(bb.x), "r"(bb.y));
            }
        }
        __syncthreads();
    }

    // epilogue: scale by dinv, quantize to fp16 message buffer
    int ra = row0 + wp * 16 + gid;       // rows gid and gid+8
    int rb = ra + 8;
    float dva = (ra < NN) ? g_dinv[ra] : 0.f;
    float dvb = (rb < NN) ? g_dinv[rb] : 0.f;
#pragma unroll
    for (int nt = 0; nt < 5; nt++) {
        int col = nt * 8 + ctid * 2;
        if (ra < NN)
            *(uint32_t*)&g_h1[(size_t)ra * CH + col] =
                pack_h2(c[nt][0] * dva, c[nt][1] * dva);
        if (rb < NN)
            *(uint32_t*)&g_h1[(size_t)rb * CH + col] =
                pack_h2(c[nt][2] * dvb, c[nt][3] * dvb);
    }
}

// ---------------------------------------------------------------------------
// Aggregation layer 1 (PULL, fp16 msgs): 5 threads/node, each owns 8 channels
// (one uint4 = 4 half2). Accumulate fp32, single fp32 write to g_acc1.
// ---------------------------------------------------------------------------
__global__ void k_agg1() {
    unsigned t = blockIdx.x * 256u + threadIdx.x;
    unsigned node = t / 5u;
    if (node >= (unsigned)NN) return;
    unsigned q = t - node * 5u;
    const uint4* base = (const uint4*)g_h1;   // node stride = 5 uint4

    float a[8];
#pragma unroll
    for (int i = 0; i < 8; i++) a[i] = 0.f;
    acc8_h(base[(size_t)node * 5 + q], a);    // self term

    int beg = g_rowstart[node];
    int len = g_deg[node];
    int i = 0;
    for (; i + 2 <= len; i += 2) {
        int s0 = __ldg(&g_csr[beg + i]);
        int s1 = __ldg(&g_csr[beg + i + 1]);
        uint4 v0 = base[(size_t)s0 * 5 + q];
        uint4 v1 = base[(size_t)s1 * 5 + q];
        acc8_h(v0, a);
        acc8_h(v1, a);
    }
    if (i < len) {
        int s0 = __ldg(&g_csr[beg + i]);
        acc8_h(base[(size_t)s0 * 5 + q], a);
    }

    float4* dst = (float4*)&g_acc1[(size_t)node * CH + q * 8];
    dst[0] = make_float4(a[0], a[1], a[2], a[3]);
    dst[1] = make_float4(a[4], a[5], a[6], a[7]);
}

// ---------------------------------------------------------------------------
// Layer-1 finish + GEMM2: r = relu(dinv*acc1 + b1); hs2 = dinv*(r @ W2) -> fp16
// ---------------------------------------------------------------------------
__global__ __launch_bounds__(128) void k_layer2(const float* __restrict__ W2,
                                                const float* __restrict__ b1) {
    __shared__ float w2s[CH * COUT];
    __shared__ float b1s[CH];
    int tid = threadIdx.x;
    for (int i = tid; i < CH * COUT; i += 128) w2s[i] = W2[i];
    if (tid < CH) b1s[tid] = b1[tid];
    __syncthreads();

    int r = blockIdx.x * 128 + tid;
    if (r >= NN) return;
    float dv = g_dinv[r];

    float rv[CH];
#pragma unroll
    for (int q = 0; q < 10; q++) {
        float4 v = *(const float4*)&g_acc1[(size_t)r * CH + q * 4];
        rv[4 * q + 0] = fmaxf(dv * v.x + b1s[4 * q + 0], 0.f);
        rv[4 * q + 1] = fmaxf(dv * v.y + b1s[4 * q + 1], 0.f);
        rv[4 * q + 2] = fmaxf(dv * v.z + b1s[4 * q + 2], 0.f);
        rv[4 * q + 3] = fmaxf(dv * v.w + b1s[4 * q + 3], 0.f);
    }

    float acc[COUT];
#pragma unroll
    for (int c = 0; c < COUT; c++) acc[c] = 0.f;
#pragma unroll
    for (int k = 0; k < CH; k++) {
        float xv = rv[k];
#pragma unroll
        for (int c = 0; c < COUT; c++)
            acc[c] = fmaf(xv, w2s[k * COUT + c], acc[c]);
    }

#pragma unroll
    for (int p = 0; p < 10; p++) {
        __half2 h = __floats2half2_rn(dv * acc[2 * p], dv * acc[2 * p + 1]);
        *(__half2*)&g_h2[(size_t)r * COUT + 2 * p] = h;
    }
}

// ---------------------------------------------------------------------------
// Aggregation layer 2 (PULL, fp16 msgs) fused with final epilogue:
// 5 threads/node, each owns 4 channels (uint2 = 2 half2).
// out = dinv * (self + sum neighbors) + b2
// ---------------------------------------------------------------------------
__global__ void k_agg2(float* __restrict__ out, const float* __restrict__ b2) {
    unsigned t = blockIdx.x * 256u + threadIdx.x;
    unsigned node = t / 5u;
    if (node >= (unsigned)NN) return;
    unsigned q = t - node * 5u;
    const uint2* base = (const uint2*)g_h2;   // node stride = 5 uint2

    float a[4];
#pragma unroll
    for (int i = 0; i < 4; i++) a[i] = 0.f;
    acc4_h(base[(size_t)node * 5 + q], a);    // self term

    int beg = g_rowstart[node];
    int len = g_deg[node];
    int i = 0;
    for (; i + 2 <= len; i += 2) {
        int s0 = __ldg(&g_csr[beg + i]);
        int s1 = __ldg(&g_csr[beg + i + 1]);
        uint2 v0 = base[(size_t)s0 * 5 + q];
        uint2 v1 = base[(size_t)s1 * 5 + q];
        acc4_h(v0, a);
        acc4_h(v1, a);
    }
    if (i < len) {
        int s0 = __ldg(&g_csr[beg + i]);
        acc4_h(base[(size_t)s0 * 5 + q], a);
    }

    float dv = g_dinv[node];
    float4 b = *(const float4*)&b2[q * 4];
    float4 o = make_float4(dv * a[0] + b.x, dv * a[1] + b.y,
                           dv * a[2] + b.z, dv * a[3] + b.w);
    ((float4*)out)[(size_t)node * 5 + q] = o;
}

// ---------------------------------------------------------------------------
extern "C" void kernel_launch(void* const* d_in, const int* in_sizes, int n_in,
                              void* d_out, int out_size) {
    const float* x  = (const float*)d_in[0];
    const int*   ei = (const int*)d_in[1];
    const float* W1 = (const float*)d_in[2];
    const float* b1 = (const float*)d_in[3];
    const float* W2 = (const float*)d_in[4];
    const float* b2 = (const float*)d_in[5];
    float* out = (float*)d_out;

    k_deg_init<<<(NN + 255) / 256, 256>>>();
    k_deg_count<<<(NE + 255) / 256, 256>>>(ei);
    k_dinv<<<(NN + 255) / 256, 256>>>();
    k_wfrag<<<(32 * 5 * 32 + 255) / 256, 256>>>(W1);
    k_scan1<<<SCAN_NB, SCAN_B>>>();
    k_scan2<<<1, 128>>>();
    k_scan3<<<SCAN_NB, SCAN_B>>>();
    k_fill<<<(NE + 255) / 256, 256>>>(ei);
    k_gemm1<<<(NN + RT - 1) / RT, 256>>>(x);
    {
        long long th = (long long)NN * 5;
        k_agg1<<<(unsigned)((th + 255) / 256), 256>>>();
    }
    k_layer2<<<(NN + 127) / 128, 128>>>(W2, b1);
    {
        long long th = (long long)NN * 5;
        k_agg2<<<(unsigned)((th + 255) / 256), 256>>>(out, b2);
    }
}